// round 1
// baseline (speedup 1.0000x reference)
#include <cuda_runtime.h>
#include <math.h>

#define H 4096
#define EPS 1e-5f
#define ROWS_PER_BLOCK 8

// Scratch for z = W @ x (5H floats). __device__ global: no allocation allowed.
__device__ float g_z[5 * H];

// ---------------------------------------------------------------------------
// Kernel 1: GEMV  z[r] = dot(W[r, 0:2H], x)  where x = concat(h0, h1)
// One warp per output row; x staged in shared memory once per block.
// ---------------------------------------------------------------------------
__global__ __launch_bounds__(256, 4)
void gemv_kernel(const float* __restrict__ h0,
                 const float* __restrict__ h1,
                 const float* __restrict__ W)
{
    __shared__ float xs[2 * H];

    const int tid = threadIdx.x;

    // Stage x = [h0; h1] into shared (float4, coalesced)
    const float4* h0v = reinterpret_cast<const float4*>(h0);
    const float4* h1v = reinterpret_cast<const float4*>(h1);
    float4* xsv = reinterpret_cast<float4*>(xs);
    #pragma unroll
    for (int i = tid; i < H / 4; i += 256) {
        xsv[i]         = h0v[i];
        xsv[i + H / 4] = h1v[i];
    }
    __syncthreads();

    const int warp = tid >> 5;
    const int lane = tid & 31;
    const int row  = blockIdx.x * ROWS_PER_BLOCK + warp;

    const float4* wrow = reinterpret_cast<const float4*>(W + (size_t)row * (2 * H));

    // 2H/4 = 2048 float4 per row; 64 per lane. 4 independent FMA chains.
    float a0 = 0.f, a1 = 0.f, a2 = 0.f, a3 = 0.f;
    #pragma unroll 8
    for (int i = lane; i < (2 * H) / 4; i += 32) {
        float4 w = wrow[i];
        float4 x = xsv[i];
        a0 = fmaf(w.x, x.x, a0);
        a1 = fmaf(w.y, x.y, a1);
        a2 = fmaf(w.z, x.z, a2);
        a3 = fmaf(w.w, x.w, a3);
    }
    float s = (a0 + a1) + (a2 + a3);
    #pragma unroll
    for (int off = 16; off > 0; off >>= 1)
        s += __shfl_down_sync(0xffffffffu, s, off);

    if (lane == 0) g_z[row] = s;
}

// ---------------------------------------------------------------------------
// Kernel 2: fused epilogue. One block, 1024 threads, thread t owns elements
// [4t, 4t+3] of every 4096-wide vector.
//
// parts: 0=f0, 1=f1, 2=i, 3=o (sigmoid(LN)), 4=u (tanh(LN))
// cell  = i*u + f0*c0 + f1*c1 ; new_cell = LN(cell); hidden = o*tanh(new_cell)
// out = [hidden(4096) ; new_cell(4096)]
// ---------------------------------------------------------------------------
__device__ __forceinline__ float sigmoidf_(float x) {
    return 1.0f / (1.0f + __expf(-x));
}

__global__ __launch_bounds__(1024, 1)
void epilogue_kernel(const float* __restrict__ c0,
                     const float* __restrict__ c1,
                     const float* __restrict__ ffio_g,
                     const float* __restrict__ ffio_b,
                     const float* __restrict__ u_g,
                     const float* __restrict__ u_b,
                     const float* __restrict__ c_g,
                     const float* __restrict__ c_b,
                     float* __restrict__ out)
{
    const int t    = threadIdx.x;   // 0..1023
    const int warp = t >> 5;
    const int lane = t & 31;

    __shared__ float red_s[6][32];
    __shared__ float red_q[6][32];
    __shared__ float stat_mean[6];
    __shared__ float stat_rstd[6];

    // Load the 5 z-parts: 4 contiguous floats per thread per part.
    float v[5][4];
    #pragma unroll
    for (int p = 0; p < 5; p++) {
        float4 vv = reinterpret_cast<const float4*>(g_z + p * H)[t];
        v[p][0] = vv.x; v[p][1] = vv.y; v[p][2] = vv.z; v[p][3] = vv.w;
    }

    // Per-part partial reductions (sum, sum of squares) -> per-warp -> smem
    #pragma unroll
    for (int p = 0; p < 5; p++) {
        float s = (v[p][0] + v[p][1]) + (v[p][2] + v[p][3]);
        float q = fmaf(v[p][0], v[p][0], fmaf(v[p][1], v[p][1],
                  fmaf(v[p][2], v[p][2], v[p][3] * v[p][3])));
        #pragma unroll
        for (int off = 16; off > 0; off >>= 1) {
            s += __shfl_down_sync(0xffffffffu, s, off);
            q += __shfl_down_sync(0xffffffffu, q, off);
        }
        if (lane == 0) { red_s[p][warp] = s; red_q[p][warp] = q; }
    }
    __syncthreads();

    // Warps 0..4 finalize part p = warp
    if (warp < 5) {
        float s = red_s[warp][lane];
        float q = red_q[warp][lane];
        #pragma unroll
        for (int off = 16; off > 0; off >>= 1) {
            s += __shfl_down_sync(0xffffffffu, s, off);
            q += __shfl_down_sync(0xffffffffu, q, off);
        }
        if (lane == 0) {
            float mean = s * (1.0f / H);
            float var  = q * (1.0f / H) - mean * mean;
            stat_mean[warp] = mean;
            stat_rstd[warp] = rsqrtf(var + EPS);
        }
    }
    __syncthreads();

    // Gates + u + cell
    float4 c0v = reinterpret_cast<const float4*>(c0)[t];
    float4 c1v = reinterpret_cast<const float4*>(c1)[t];
    float c0a[4] = {c0v.x, c0v.y, c0v.z, c0v.w};
    float c1a[4] = {c1v.x, c1v.y, c1v.z, c1v.w};

    float gate[4][4];   // f0, f1, i, o
    #pragma unroll
    for (int p = 0; p < 4; p++) {
        float4 gv = reinterpret_cast<const float4*>(ffio_g + p * H)[t];
        float4 bv = reinterpret_cast<const float4*>(ffio_b + p * H)[t];
        float ga[4] = {gv.x, gv.y, gv.z, gv.w};
        float ba[4] = {bv.x, bv.y, bv.z, bv.w};
        float m = stat_mean[p], r = stat_rstd[p];
        #pragma unroll
        for (int k = 0; k < 4; k++)
            gate[p][k] = sigmoidf_(fmaf((v[p][k] - m) * r, ga[k], ba[k]));
    }

    float uval[4];
    {
        float4 gv = reinterpret_cast<const float4*>(u_g)[t];
        float4 bv = reinterpret_cast<const float4*>(u_b)[t];
        float ga[4] = {gv.x, gv.y, gv.z, gv.w};
        float ba[4] = {bv.x, bv.y, bv.z, bv.w};
        float m = stat_mean[4], r = stat_rstd[4];
        #pragma unroll
        for (int k = 0; k < 4; k++)
            uval[k] = tanhf(fmaf((v[4][k] - m) * r, ga[k], ba[k]));
    }

    float cell[4];
    #pragma unroll
    for (int k = 0; k < 4; k++)
        cell[k] = fmaf(gate[2][k], uval[k],
                  fmaf(gate[0][k], c0a[k], gate[1][k] * c1a[k]));

    // Reduce cell for its LayerNorm
    {
        float s = (cell[0] + cell[1]) + (cell[2] + cell[3]);
        float q = fmaf(cell[0], cell[0], fmaf(cell[1], cell[1],
                  fmaf(cell[2], cell[2], cell[3] * cell[3])));
        #pragma unroll
        for (int off = 16; off > 0; off >>= 1) {
            s += __shfl_down_sync(0xffffffffu, s, off);
            q += __shfl_down_sync(0xffffffffu, q, off);
        }
        if (lane == 0) { red_s[5][warp] = s; red_q[5][warp] = q; }
    }
    __syncthreads();
    if (warp == 5) {
        float s = red_s[5][lane];
        float q = red_q[5][lane];
        #pragma unroll
        for (int off = 16; off > 0; off >>= 1) {
            s += __shfl_down_sync(0xffffffffu, s, off);
            q += __shfl_down_sync(0xffffffffu, q, off);
        }
        if (lane == 0) {
            float mean = s * (1.0f / H);
            float var  = q * (1.0f / H) - mean * mean;
            stat_mean[5] = mean;
            stat_rstd[5] = rsqrtf(var + EPS);
        }
    }
    __syncthreads();

    // Final outputs
    float4 cgv = reinterpret_cast<const float4*>(c_g)[t];
    float4 cbv = reinterpret_cast<const float4*>(c_b)[t];
    float cga[4] = {cgv.x, cgv.y, cgv.z, cgv.w};
    float cba[4] = {cbv.x, cbv.y, cbv.z, cbv.w};
    float m = stat_mean[5], r = stat_rstd[5];

    float4 hid, ncl;
    float nc[4], hd[4];
    #pragma unroll
    for (int k = 0; k < 4; k++) {
        nc[k] = fmaf((cell[k] - m) * r, cga[k], cba[k]);
        hd[k] = gate[3][k] * tanhf(nc[k]);
    }
    hid.x = hd[0]; hid.y = hd[1]; hid.z = hd[2]; hid.w = hd[3];
    ncl.x = nc[0]; ncl.y = nc[1]; ncl.z = nc[2]; ncl.w = nc[3];

    reinterpret_cast<float4*>(out)[t]            = hid;   // new_hidden
    reinterpret_cast<float4*>(out + H)[t]        = ncl;   // new_cell
}

// ---------------------------------------------------------------------------
// Launch
// Inputs (metadata order): 0=h0, 1=c0, 2=h1, 3=c1, 4=W,
//   5=ffio_g(4H), 6=ffio_b(4H), 7=u_g, 8=u_b, 9=c_g, 10=c_b
// Output: [new_hidden(4096); new_cell(4096)] fp32
// ---------------------------------------------------------------------------
extern "C" void kernel_launch(void* const* d_in, const int* in_sizes, int n_in,
                              void* d_out, int out_size)
{
    const float* h0     = (const float*)d_in[0];
    const float* c0     = (const float*)d_in[1];
    const float* h1     = (const float*)d_in[2];
    const float* c1     = (const float*)d_in[3];
    const float* W      = (const float*)d_in[4];
    const float* ffio_g = (const float*)d_in[5];
    const float* ffio_b = (const float*)d_in[6];
    const float* u_g    = (const float*)d_in[7];
    const float* u_b    = (const float*)d_in[8];
    const float* c_g    = (const float*)d_in[9];
    const float* c_b    = (const float*)d_in[10];
    float* out = (float*)d_out;

    const int rows = 5 * H;                       // 20480
    gemv_kernel<<<rows / ROWS_PER_BLOCK, 256>>>(h0, h1, W);
    epilogue_kernel<<<1, 1024>>>(c0, c1, ffio_g, ffio_b, u_g, u_b, c_g, c_b, out);
}